// round 16
// baseline (speedup 1.0000x reference)
#include <cuda_runtime.h>
#include <cuda_bf16.h>
#include <cstdint>
#include <cstddef>

#define NMAX 100000
#define EMAX 3200000
#define NBLK_SCAN ((NMAX + 1023) / 1024)

// ---------------- static device scratch (no allocation anywhere) -------------
__device__ __align__(128) float g_h1[(size_t)NMAX * 256];   // relu(x@W1+b1)
__device__ __align__(128) float g_h [(size_t)NMAX * 64];    // MLP output (fp32)
__device__ __align__(128) __nv_bfloat162 g_hb0[(size_t)NMAX * 32]; // prop state A
__device__ __align__(128) __nv_bfloat162 g_hb1[(size_t)NMAX * 32]; // prop state B
__device__ __align__(128) float g_dis[NMAX];
__device__ __align__(128) int   g_cnt[NMAX];
__device__ __align__(128) int   g_incl[NMAX];
__device__ __align__(128) int   g_bsum[NBLK_SCAN + 1];
__device__ __align__(128) int   g_rowptr[NMAX + 1];
__device__ __align__(128) int   g_cursor[NMAX];
__device__ __align__(128) int   g_col[EMAX];
__device__ __align__(128) float g_w[EMAX];
__device__ int g_is64;

// ---------------- dtype detection --------------------------------------------
__global__ void k_detect(const void* ei, int E, int N) {
    __shared__ int bad;
    if (threadIdx.x == 0) bad = 0;
    __syncthreads();
    const long long* p = (const long long*)ei;
    int lim = (E < 4096) ? E : 4096;
    for (int i = threadIdx.x; i < lim; i += blockDim.x) {
        long long v = p[i];
        if (v < 0 || v >= (long long)N) bad = 1;
    }
    __syncthreads();
    if (threadIdx.x == 0) g_is64 = bad ? 0 : 1;
}

__device__ __forceinline__ int edge_at(const void* ei, size_t j, int N) {
    long long v;
    if (g_is64) v = ((const long long*)ei)[j];
    else        v = (long long)((const int*)ei)[j];
    if (v < 0) v = 0;
    if (v >= N) v = N - 1;
    return (int)v;
}

// ---------------- SGEMM with vectorized smem reads ---------------------------
// SEL==0 : A = param (x),  C = g_h1, ReLU      SEL==1 : A = g_h1, C = g_h
template<int BM, int BN, int BK, int TM, int TN, int SEL>
__global__ void __launch_bounds__(256) sgemm_kernel(
        const float* __restrict__ A_in,
        const float* __restrict__ B,
        const float* __restrict__ bias,
        int M, int N, int K) {
    constexpr int NT = (BM / TM) * (BN / TN);
    constexpr bool RELU = (SEL == 0);
    const float* A = (SEL == 0) ? A_in : (const float*)g_h1;
    float* C       = (SEL == 0) ? g_h1 : g_h;

    __shared__ float As[BK][BM];
    __shared__ float Bs[BK][BN];

    const int tid  = threadIdx.x;
    const int row0 = blockIdx.y * BM;
    const int col0 = blockIdx.x * BN;

    const int tcols = BN / TN;
    const int tr = tid / tcols;
    const int tc = tid % tcols;

    float acc[TM][TN];
    #pragma unroll
    for (int i = 0; i < TM; i++)
        #pragma unroll
        for (int j = 0; j < TN; j++) acc[i][j] = 0.0f;

    constexpr int A_LD = (BM * BK) / (NT * 4);
    constexpr int B_LD = (BK * BN) / (NT * 4);

    for (int kt = 0; kt < K; kt += BK) {
        #pragma unroll
        for (int i = 0; i < A_LD; i++) {
            int idx = tid + i * NT;
            int a_r = idx / (BK / 4);
            int a_c = (idx % (BK / 4)) * 4;
            float4 v = make_float4(0.f, 0.f, 0.f, 0.f);
            int gr = row0 + a_r;
            if (gr < M)
                v = *reinterpret_cast<const float4*>(A + (size_t)gr * K + kt + a_c);
            As[a_c + 0][a_r] = v.x;
            As[a_c + 1][a_r] = v.y;
            As[a_c + 2][a_r] = v.z;
            As[a_c + 3][a_r] = v.w;
        }
        #pragma unroll
        for (int i = 0; i < B_LD; i++) {
            int idx = tid + i * NT;
            int b_r = idx / (BN / 4);
            int b_c = (idx % (BN / 4)) * 4;
            float4 v = *reinterpret_cast<const float4*>(B + (size_t)(kt + b_r) * N + col0 + b_c);
            *reinterpret_cast<float4*>(&Bs[b_r][b_c]) = v;
        }
        __syncthreads();

        #pragma unroll
        for (int kk = 0; kk < BK; kk++) {
            // vectorized smem reads: 2x LDS.128 for A row-slice (broadcast
            // within phase), TN/4 x LDS.128 for B col-slice.
            float4 a0 = *reinterpret_cast<const float4*>(&As[kk][tr * TM]);
            float4 a1 = *reinterpret_cast<const float4*>(&As[kk][tr * TM + 4]);
            float4 b0 = *reinterpret_cast<const float4*>(&Bs[kk][tc * TN]);
            float ar[TM], br[TN];
            ar[0] = a0.x; ar[1] = a0.y; ar[2] = a0.z; ar[3] = a0.w;
            ar[4] = a1.x; ar[5] = a1.y; ar[6] = a1.z; ar[7] = a1.w;
            br[0] = b0.x; br[1] = b0.y; br[2] = b0.z; br[3] = b0.w;
            if (TN == 8) {
                float4 b1 = *reinterpret_cast<const float4*>(&Bs[kk][tc * TN + 4]);
                br[4] = b1.x; br[5] = b1.y; br[6] = b1.z; br[7] = b1.w;
            }
            #pragma unroll
            for (int i = 0; i < TM; i++)
                #pragma unroll
                for (int j = 0; j < TN; j++)
                    acc[i][j] = fmaf(ar[i], br[j], acc[i][j]);
        }
        __syncthreads();
    }

    #pragma unroll
    for (int i = 0; i < TM; i++) {
        int gr = row0 + tr * TM + i;
        if (gr >= M) continue;
        #pragma unroll
        for (int j = 0; j < TN; j += 4) {
            int gc = col0 + tc * TN + j;
            float4 b4 = *reinterpret_cast<const float4*>(bias + gc);
            float4 v;
            v.x = acc[i][j + 0] + b4.x;
            v.y = acc[i][j + 1] + b4.y;
            v.z = acc[i][j + 2] + b4.z;
            v.w = acc[i][j + 3] + b4.w;
            if (RELU) {
                v.x = fmaxf(v.x, 0.f); v.y = fmaxf(v.y, 0.f);
                v.z = fmaxf(v.z, 0.f); v.w = fmaxf(v.w, 0.f);
            }
            *reinterpret_cast<float4*>(C + (size_t)gr * N + gc) = v;
        }
    }
}

// ---------------- CSR construction -------------------------------------------
__global__ void k_zero_cnt(int n) {
    int i = blockIdx.x * blockDim.x + threadIdx.x;
    if (i < n) g_cnt[i] = 0;
}
__global__ void k_count(const void* __restrict__ ei, int E, int N) {
    int e = blockIdx.x * blockDim.x + threadIdx.x;
    if (e < E) atomicAdd(&g_cnt[edge_at(ei, (size_t)E + e, N)], 1);
}
__global__ void k_dis(int n) {
    int i = blockIdx.x * blockDim.x + threadIdx.x;
    if (i < n) g_dis[i] = rsqrtf((float)(g_cnt[i] + 1));
}
__global__ void k_scan1(int N) {
    __shared__ int sh[1024];
    int i = blockIdx.x * 1024 + threadIdx.x;
    int v = (i < N) ? g_cnt[i] : 0;
    sh[threadIdx.x] = v;
    __syncthreads();
    #pragma unroll
    for (int off = 1; off < 1024; off <<= 1) {
        int t = 0;
        if ((int)threadIdx.x >= off) t = sh[threadIdx.x - off];
        __syncthreads();
        sh[threadIdx.x] += t;
        __syncthreads();
    }
    if (i < N) g_incl[i] = sh[threadIdx.x];
    if (threadIdx.x == 1023) g_bsum[blockIdx.x] = sh[1023];
}
__global__ void k_scan2(int nb) {
    if (threadIdx.x == 0 && blockIdx.x == 0) {
        int acc = 0;
        for (int b = 0; b < nb; b++) { int v = g_bsum[b]; g_bsum[b] = acc; acc += v; }
    }
}
__global__ void k_scan3(int N) {
    int i = blockIdx.x * 1024 + threadIdx.x;
    if (i < N) {
        int inc = g_incl[i] + g_bsum[i / 1024];
        g_rowptr[i + 1] = inc;
        g_cursor[i] = inc - g_cnt[i];
    }
    if (i == 0) g_rowptr[0] = 0;
}
__global__ void k_fillcsr(const void* __restrict__ ei, int E, int N) {
    int e = blockIdx.x * blockDim.x + threadIdx.x;
    if (e >= E) return;
    int s = edge_at(ei, (size_t)e, N);
    int d = edge_at(ei, (size_t)E + e, N);
    int p = atomicAdd(&g_cursor[d], 1);
    if (p >= 0 && p < EMAX) {
        g_col[p] = s;
        g_w[p] = g_dis[s] * g_dis[d];
    }
}

// ---------------- propagation (bf16 state, fp32 accumulate) ------------------
// out = temp[0]*h ; hb0 = bf16(h)
__global__ void k_init(float* __restrict__ out, const float* __restrict__ temp,
                       int n16) {
    int i = blockIdx.x * blockDim.x + threadIdx.x;
    if (i >= n16) return;
    float t0 = temp[0];
    float4 v = reinterpret_cast<const float4*>(g_h)[i];
    reinterpret_cast<float4*>(out)[i] =
        make_float4(t0 * v.x, t0 * v.y, t0 * v.z, t0 * v.w);
    int node = i >> 4, f = i & 15;
    size_t b = (size_t)node * 32 + (size_t)f * 2;
    g_hb0[b]     = __floats2bfloat162_rn(v.x, v.y);
    g_hb0[b + 1] = __floats2bfloat162_rn(v.z, v.w);
}

__device__ __forceinline__ float2 bf2f(uint32_t u) {
    return __bfloat1622float2(*reinterpret_cast<const __nv_bfloat162*>(&u));
}

// nxt[row] = dis^2*cur[row] + sum_n w[n]*cur[col[n]]   (bf16 gather, fp32 acc)
// out[row] += temp[k]*accum (exact fp32 accumulator, pre-rounding)
// 8 threads per row; each handles 8 features (one uint4 = 4 x bf162).
__global__ void k_prop(int curi, float* __restrict__ out,
                       const float* __restrict__ temp, int k, int N) {
    int t = blockIdx.x * blockDim.x + threadIdx.x;
    int row = t >> 3;
    if (row >= N) return;
    int f = t & 7;

    const __nv_bfloat162* cur = curi ? g_hb1 : g_hb0;
    __nv_bfloat162*       nxt = curi ? g_hb0 : g_hb1;

    float d = g_dis[row];
    float d2 = d * d;
    size_t base = (size_t)row * 32 + (size_t)f * 4;   // 4 bf162 per thread

    float acc[8];
    {
        uint4 u = *reinterpret_cast<const uint4*>(cur + base);
        float2 p0 = bf2f(u.x), p1 = bf2f(u.y), p2 = bf2f(u.z), p3 = bf2f(u.w);
        acc[0] = d2 * p0.x; acc[1] = d2 * p0.y;
        acc[2] = d2 * p1.x; acc[3] = d2 * p1.y;
        acc[4] = d2 * p2.x; acc[5] = d2 * p2.y;
        acc[6] = d2 * p3.x; acc[7] = d2 * p3.y;
    }

    int beg = g_rowptr[row];
    int end = g_rowptr[row + 1];
    #pragma unroll 4
    for (int n = beg; n < end; n++) {
        int s = __ldg(&g_col[n]);
        float w = __ldg(&g_w[n]);
        uint4 u = *reinterpret_cast<const uint4*>(cur + (size_t)s * 32 + (size_t)f * 4);
        float2 p0 = bf2f(u.x), p1 = bf2f(u.y), p2 = bf2f(u.z), p3 = bf2f(u.w);
        acc[0] = fmaf(w, p0.x, acc[0]); acc[1] = fmaf(w, p0.y, acc[1]);
        acc[2] = fmaf(w, p1.x, acc[2]); acc[3] = fmaf(w, p1.y, acc[3]);
        acc[4] = fmaf(w, p2.x, acc[4]); acc[5] = fmaf(w, p2.y, acc[5]);
        acc[6] = fmaf(w, p3.x, acc[6]); acc[7] = fmaf(w, p3.y, acc[7]);
    }

    {   // store bf16 state
        __nv_bfloat162 o0 = __floats2bfloat162_rn(acc[0], acc[1]);
        __nv_bfloat162 o1 = __floats2bfloat162_rn(acc[2], acc[3]);
        __nv_bfloat162 o2 = __floats2bfloat162_rn(acc[4], acc[5]);
        __nv_bfloat162 o3 = __floats2bfloat162_rn(acc[6], acc[7]);
        uint4 pk;
        pk.x = *reinterpret_cast<uint32_t*>(&o0);
        pk.y = *reinterpret_cast<uint32_t*>(&o1);
        pk.z = *reinterpret_cast<uint32_t*>(&o2);
        pk.w = *reinterpret_cast<uint32_t*>(&o3);
        *reinterpret_cast<uint4*>(nxt + base) = pk;
    }

    float tk = temp[k];
    size_t oi = (size_t)row * 64 + (size_t)f * 8;
    float4 o0 = *reinterpret_cast<const float4*>(out + oi);
    float4 o1 = *reinterpret_cast<const float4*>(out + oi + 4);
    o0.x = fmaf(tk, acc[0], o0.x); o0.y = fmaf(tk, acc[1], o0.y);
    o0.z = fmaf(tk, acc[2], o0.z); o0.w = fmaf(tk, acc[3], o0.w);
    o1.x = fmaf(tk, acc[4], o1.x); o1.y = fmaf(tk, acc[5], o1.y);
    o1.z = fmaf(tk, acc[6], o1.z); o1.w = fmaf(tk, acc[7], o1.w);
    *reinterpret_cast<float4*>(out + oi)     = o0;
    *reinterpret_cast<float4*>(out + oi + 4) = o1;
}

// ---------------- launch ------------------------------------------------------
extern "C" void kernel_launch(void* const* d_in, const int* in_sizes, int n_in,
                              void* d_out, int out_size) {
    const float* x    = (const float*)d_in[0];
    const void*  ei   = (const void*)d_in[1];
    const float* W1   = (const float*)d_in[2];
    const float* b1   = (const float*)d_in[3];
    const float* W2   = (const float*)d_in[4];
    const float* b2   = (const float*)d_in[5];
    const float* temp = (const float*)d_in[6];
    float* out = (float*)d_out;

    const int HID = in_sizes[3];                 // 256
    const int OUT = in_sizes[5];                 // 64
    const int INF = in_sizes[2] / HID;           // 512
    const int N   = in_sizes[0] / INF;           // 100000
    const int E   = in_sizes[1] / 2;             // 3200000

    k_detect  <<<1, 256>>>(ei, E, N);                               // 1
    k_zero_cnt<<<(N + 255) / 256, 256>>>(N);                        // 2
    k_count   <<<(E + 255) / 256, 256>>>(ei, E, N);                 // 3

    {   // GEMM1: x[N,512] @ W1[512,256] -> g_h1 (relu)
        dim3 g(HID / 128, (N + 127) / 128);
        sgemm_kernel<128, 128, 16, 8, 8, 0><<<g, 256>>>(x, W1, b1, N, HID, INF); // 4
    }
    {   // GEMM2: g_h1[N,256] @ W2[256,64] -> g_h
        dim3 g(OUT / 64, (N + 127) / 128);
        sgemm_kernel<128, 64, 16, 8, 4, 1><<<g, 256>>>(nullptr, W2, b2, N, OUT, HID); // 5
    }

    k_dis    <<<(N + 255) / 256, 256>>>(N);                         // 6
    const int nblk = (N + 1023) / 1024;
    k_scan1  <<<nblk, 1024>>>(N);
    k_scan2  <<<1, 32>>>(nblk);
    k_scan3  <<<nblk, 1024>>>(N);
    k_fillcsr<<<(E + 255) / 256, 256>>>(ei, E, N);

    const int n16 = N * 16;
    k_init<<<(n16 + 255) / 256, 256>>>(out, temp, n16);

    // iter k reads hb[cur], writes hb[1-cur]; cur starts at 0 (k_init wrote hb0)
    const int n8 = N * 8;
    int cur = 0;
    for (int k = 1; k <= 10; k++) {
        k_prop<<<(n8 + 255) / 256, 256>>>(cur, out, temp, k, N);
        cur ^= 1;
    }
}